// round 2
// baseline (speedup 1.0000x reference)
#include <cuda_runtime.h>
#include <math.h>

// Problem constants
#define B_   4
#define S_   2048
#define D_   1024
#define E_   1024
#define NH_  16
#define HD_  64
#define QKV_N (3 * E_)       // 3072
#define M_TOT (B_ * S_)      // 8192

// Scratch (device globals — allocation-free per harness rules)
__device__ float g_qkv[(size_t)M_TOT * QKV_N];   // [8192, 3072]
__device__ float g_vals[(size_t)M_TOT * E_];     // [8192, 1024]

// ----------------------------------------------------------------------------
// SGEMM: C[M,N] = A[M,K] @ B[N,K]^T   (both operands K-contiguous, row-major)
// 128x128 block tile, BK=16, 256 threads, 8x8 per-thread micro tile.
// ----------------------------------------------------------------------------
__global__ __launch_bounds__(256) void sgemm_nt(
    const float* __restrict__ A, const float* __restrict__ Bm,
    float* __restrict__ C, int M, int N, int K)
{
    const int BM = 128, BN = 128, BK = 16;
    __shared__ float As[BK][BM];   // [k][m]
    __shared__ float Bs[BK][BN];   // [k][n]

    int tid = threadIdx.x;
    int tx = tid & 15;
    int ty = tid >> 4;
    int m0 = blockIdx.y * BM;
    int n0 = blockIdx.x * BN;

    float acc[8][8];
#pragma unroll
    for (int i = 0; i < 8; i++)
#pragma unroll
        for (int j = 0; j < 8; j++) acc[i][j] = 0.f;

    for (int kt = 0; kt < K; kt += BK) {
        // Load A and B tiles (transposed into smem). 512 float4 each.
#pragma unroll
        for (int p = 0; p < 2; ++p) {
            int idx = tid + p * 256;       // 0..511
            int r   = idx >> 2;            // row within tile (0..127)
            int c4  = idx & 3;             // float4 column (0..3)
            float4 va = *(const float4*)(A  + (size_t)(m0 + r) * K + kt + c4 * 4);
            As[c4 * 4 + 0][r] = va.x; As[c4 * 4 + 1][r] = va.y;
            As[c4 * 4 + 2][r] = va.z; As[c4 * 4 + 3][r] = va.w;
            float4 vb = *(const float4*)(Bm + (size_t)(n0 + r) * K + kt + c4 * 4);
            Bs[c4 * 4 + 0][r] = vb.x; Bs[c4 * 4 + 1][r] = vb.y;
            Bs[c4 * 4 + 2][r] = vb.z; Bs[c4 * 4 + 3][r] = vb.w;
        }
        __syncthreads();

#pragma unroll
        for (int k = 0; k < BK; ++k) {
            float a[8], b[8];
            *(float4*)&a[0] = *(const float4*)&As[k][ty * 8];
            *(float4*)&a[4] = *(const float4*)&As[k][ty * 8 + 4];
            *(float4*)&b[0] = *(const float4*)&Bs[k][tx * 8];
            *(float4*)&b[4] = *(const float4*)&Bs[k][tx * 8 + 4];
#pragma unroll
            for (int i = 0; i < 8; i++)
#pragma unroll
                for (int j = 0; j < 8; j++)
                    acc[i][j] += a[i] * b[j];
        }
        __syncthreads();
    }

#pragma unroll
    for (int i = 0; i < 8; i++) {
        float4* cp = (float4*)(C + (size_t)(m0 + ty * 8 + i) * N + n0 + tx * 8);
        float4 v0 = make_float4(acc[i][0], acc[i][1], acc[i][2], acc[i][3]);
        float4 v1 = make_float4(acc[i][4], acc[i][5], acc[i][6], acc[i][7]);
        cp[0] = v0;
        cp[1] = v1;
    }
}

// ----------------------------------------------------------------------------
// Flash attention, fp32. One CTA = one (b, h, 64-query block).
// Tiles: BM=64 queries x BN=64 keys, HD=64. 256 threads, 4x4 micro tiles.
// Smem exactly 48KB: Qs (K-major) + KP (K tile, reused as P tile) + Vs.
// ----------------------------------------------------------------------------
__global__ __launch_bounds__(256) void attn_kernel(
    const float* __restrict__ qkv, float* __restrict__ vals)
{
    __shared__ float Qs[HD_][64];  // [d][m], pre-scaled by 1/sqrt(HD)
    __shared__ float KP[64][64];   // K phase: [d][n]; P phase: [m][n]
    __shared__ float Vs[64][64];   // [n][d]

    int tid = threadIdx.x;
    int tx = tid & 15;
    int ty = tid >> 4;
    int qb = blockIdx.x;
    int h  = blockIdx.y;
    int b  = blockIdx.z;

    const float* qbase = qkv + (size_t)b * S_ * QKV_N + h * (3 * HD_);

    // Load Q block, transposed + scaled. idx -> (n=seq row, d4=float4 col).
#pragma unroll
    for (int p = 0; p < 4; ++p) {
        int idx = tid + p * 256;                 // 0..1023
        int n  = (idx >> 1) & 63;
        int d4 = (idx & 1) + ((idx >> 7) << 1);  // 0..15
        float4 v = *(const float4*)(qbase + (size_t)(qb * 64 + n) * QKV_N + d4 * 4);
        Qs[d4 * 4 + 0][n] = v.x * 0.125f;
        Qs[d4 * 4 + 1][n] = v.y * 0.125f;
        Qs[d4 * 4 + 2][n] = v.z * 0.125f;
        Qs[d4 * 4 + 3][n] = v.w * 0.125f;
    }

    float m_i[4], l_i[4], o[4][4];
#pragma unroll
    for (int i = 0; i < 4; i++) {
        m_i[i] = -1e30f;
        l_i[i] = 0.f;
#pragma unroll
        for (int j = 0; j < 4; j++) o[i][j] = 0.f;
    }

    for (int nt = 0; nt < S_; nt += 64) {
        __syncthreads();  // previous iteration's PV reads of KP/Vs are done

        // Load K tile (transposed into KP) and V tile (direct into Vs)
#pragma unroll
        for (int p = 0; p < 4; ++p) {
            int idx = tid + p * 256;
            int n  = (idx >> 1) & 63;
            int d4 = (idx & 1) + ((idx >> 7) << 1);
            const float* krow = qbase + HD_ + (size_t)(nt + n) * QKV_N;
            float4 kv = *(const float4*)(krow + d4 * 4);
            KP[d4 * 4 + 0][n] = kv.x; KP[d4 * 4 + 1][n] = kv.y;
            KP[d4 * 4 + 2][n] = kv.z; KP[d4 * 4 + 3][n] = kv.w;
            const float* vrow = qbase + 2 * HD_ + (size_t)(nt + n) * QKV_N;
            *(float4*)&Vs[n][d4 * 4] = *(const float4*)(vrow + d4 * 4);
        }
        __syncthreads();

        // S tile: s[i][j] = sum_d Qs[d][ty*4+i] * KP[d][tx*4+j]
        float s[4][4];
#pragma unroll
        for (int i = 0; i < 4; i++)
#pragma unroll
            for (int j = 0; j < 4; j++) s[i][j] = 0.f;
#pragma unroll 16
        for (int d = 0; d < HD_; ++d) {
            float4 a = *(const float4*)&Qs[d][ty * 4];
            float4 bb = *(const float4*)&KP[d][tx * 4];
            float av[4] = {a.x, a.y, a.z, a.w};
            float bv[4] = {bb.x, bb.y, bb.z, bb.w};
#pragma unroll
            for (int i = 0; i < 4; i++)
#pragma unroll
                for (int j = 0; j < 4; j++)
                    s[i][j] += av[i] * bv[j];
        }

        // Online softmax. Row reductions across the 16 tx threads.
#pragma unroll
        for (int i = 0; i < 4; i++) {
            float tm = fmaxf(fmaxf(s[i][0], s[i][1]), fmaxf(s[i][2], s[i][3]));
#pragma unroll
            for (int off = 8; off >= 1; off >>= 1)
                tm = fmaxf(tm, __shfl_xor_sync(0xffffffffu, tm, off));
            float mn = fmaxf(m_i[i], tm);
            float fac = __expf(m_i[i] - mn);
            m_i[i] = mn;
            float rs = 0.f;
#pragma unroll
            for (int j = 0; j < 4; j++) {
                s[i][j] = __expf(s[i][j] - mn);   // s now holds P
                rs += s[i][j];
            }
#pragma unroll
            for (int off = 8; off >= 1; off >>= 1)
                rs += __shfl_xor_sync(0xffffffffu, rs, off);
            l_i[i] = l_i[i] * fac + rs;
#pragma unroll
            for (int j = 0; j < 4; j++) o[i][j] *= fac;
        }

        __syncthreads();  // all S-tile reads of KP(K) are done
        // Store P into KP as [m][n]
#pragma unroll
        for (int i = 0; i < 4; i++)
            *(float4*)&KP[ty * 4 + i][tx * 4] =
                make_float4(s[i][0], s[i][1], s[i][2], s[i][3]);
        __syncthreads();

        // O += P @ V : o[i][j] += sum_n KP[ty*4+i][n] * Vs[n][tx*4+j]
#pragma unroll 8
        for (int n = 0; n < 64; ++n) {
            float4 bv = *(const float4*)&Vs[n][tx * 4];
            float bvv[4] = {bv.x, bv.y, bv.z, bv.w};
            float av[4];
#pragma unroll
            for (int i = 0; i < 4; i++) av[i] = KP[ty * 4 + i][n];
#pragma unroll
            for (int i = 0; i < 4; i++)
#pragma unroll
                for (int j = 0; j < 4; j++)
                    o[i][j] += av[i] * bvv[j];
        }
    }

    // Epilogue: normalize and write vals[b, m, h*64 + d]
#pragma unroll
    for (int i = 0; i < 4; i++) {
        float inv = 1.f / l_i[i];
        size_t row = (size_t)b * S_ + qb * 64 + ty * 4 + i;
        float4 v = make_float4(o[i][0] * inv, o[i][1] * inv,
                               o[i][2] * inv, o[i][3] * inv);
        *(float4*)(vals + row * E_ + h * HD_ + tx * 4) = v;
    }
}

// ----------------------------------------------------------------------------
// Launch
// ----------------------------------------------------------------------------
extern "C" void kernel_launch(void* const* d_in, const int* in_sizes, int n_in,
                              void* d_out, int out_size)
{
    (void)in_sizes; (void)n_in; (void)out_size;
    const float* x     = (const float*)d_in[0];
    const float* qkv_w = (const float*)d_in[1];
    const float* o_w   = (const float*)d_in[2];
    float* out = (float*)d_out;

    // Resolve scratch symbol addresses ONCE (first call = correctness run,
    // outside graph capture). Subsequent captured calls are pure launches.
    static float* qkv_buf = nullptr;
    static float* vals_buf = nullptr;
    if (qkv_buf == nullptr) {
        cudaGetSymbolAddress((void**)&qkv_buf, g_qkv);
        cudaGetSymbolAddress((void**)&vals_buf, g_vals);
    }

    dim3 blk(256);
    // 1) qkv = x @ qkv_w^T : [8192,1024] x [3072,1024]^T -> [8192,3072]
    sgemm_nt<<<dim3(QKV_N / 128, M_TOT / 128), blk>>>(x, qkv_w, qkv_buf,
                                                      M_TOT, QKV_N, D_);
    // 2) attention -> vals [8192, 1024]
    attn_kernel<<<dim3(S_ / 64, NH_, B_), blk>>>(qkv_buf, vals_buf);
    // 3) out = vals @ o_w^T : [8192,1024] x [1024,1024]^T -> [8192,1024]
    sgemm_nt<<<dim3(E_ / 128, M_TOT / 128), blk>>>(vals_buf, o_w, out,
                                                   M_TOT, E_, D_);
}

// round 3
// speedup vs baseline: 1.3816x; 1.3816x over previous
#include <cuda_runtime.h>
#include <math.h>
#include <stdint.h>

// Problem constants
#define B_   4
#define S_   2048
#define D_   1024
#define E_   1024
#define NH_  16
#define HD_  64
#define QKV_N (3 * E_)       // 3072
#define M_TOT (B_ * S_)      // 8192

// Scratch (device globals — allocation-free per harness rules)
__device__ float g_qkv[(size_t)M_TOT * QKV_N];   // [8192, 3072]
__device__ float g_vals[(size_t)M_TOT * E_];     // [8192, 1024]

// ----------------------------------------------------------------------------
// tf32 helpers
// ----------------------------------------------------------------------------
__device__ __forceinline__ float to_tf32(float x) {
    uint32_t u;
    asm("cvt.rna.tf32.f32 %0, %1;" : "=r"(u) : "f"(x));
    return __uint_as_float(u);
}

__device__ __forceinline__ void mma_tf32(float* c, const uint32_t* a,
                                         const uint32_t* b) {
    asm volatile(
        "mma.sync.aligned.m16n8k8.row.col.f32.tf32.tf32.f32 "
        "{%0,%1,%2,%3},{%4,%5,%6,%7},{%8,%9},{%0,%1,%2,%3};"
        : "+f"(c[0]), "+f"(c[1]), "+f"(c[2]), "+f"(c[3])
        : "r"(a[0]), "r"(a[1]), "r"(a[2]), "r"(a[3]),
          "r"(b[0]), "r"(b[1]));
}

// ----------------------------------------------------------------------------
// TF32 tensor-core GEMM: C[M,N] = A[M,K] @ B[N,K]^T (both K-contiguous).
// 128x128 block tile, BK=16, 256 threads (8 warps as 2x4), warp tile 64x32,
// m16n8k8 mma, double-buffered smem. Smem rows padded to 136 floats so
// fragment LDS addresses land on 32 distinct banks (8*k + grp pattern).
// ----------------------------------------------------------------------------
__global__ __launch_bounds__(256) void sgemm_tf32(
    const float* __restrict__ A, const float* __restrict__ Bm,
    float* __restrict__ C, int M, int N, int K)
{
    __shared__ float As[2][16][136];
    __shared__ float Bs[2][16][136];

    int tid  = threadIdx.x;
    int lane = tid & 31;
    int warp = tid >> 5;
    int wm = warp & 1;      // 0..1 : 64-row band
    int wn = warp >> 1;     // 0..3 : 32-col band
    int tig = lane & 3;     // thread-in-group
    int grp = lane >> 2;    // group id (0..7)

    int m0 = blockIdx.y * 128;
    int n0 = blockIdx.x * 128;

    // Global-load mapping: thread -> (row = tid/4 [+64], float4-col = tid%4)
    int lr  = tid >> 2;
    int lc4 = tid & 3;
    const float* Ald = A  + (size_t)(m0 + lr) * K + lc4 * 4;
    const float* Bld = Bm + (size_t)(n0 + lr) * K + lc4 * 4;
    size_t half = (size_t)64 * K;

    float acc[4][4][4];
#pragma unroll
    for (int i = 0; i < 4; i++)
#pragma unroll
        for (int j = 0; j < 4; j++)
#pragma unroll
            for (int r = 0; r < 4; r++) acc[i][j][r] = 0.f;

    float4 ar[2], br[2];
    ar[0] = *(const float4*)(Ald);
    ar[1] = *(const float4*)(Ald + half);
    br[0] = *(const float4*)(Bld);
    br[1] = *(const float4*)(Bld + half);

    // STS with tf32 conversion, transposed to [k][m] / [k][n]
    auto sts_tiles = [&](int buf) {
#pragma unroll
        for (int p = 0; p < 2; ++p) {
            int row = lr + p * 64;
            float4 va = ar[p];
            As[buf][lc4 * 4 + 0][row] = to_tf32(va.x);
            As[buf][lc4 * 4 + 1][row] = to_tf32(va.y);
            As[buf][lc4 * 4 + 2][row] = to_tf32(va.z);
            As[buf][lc4 * 4 + 3][row] = to_tf32(va.w);
            float4 vb = br[p];
            Bs[buf][lc4 * 4 + 0][row] = to_tf32(vb.x);
            Bs[buf][lc4 * 4 + 1][row] = to_tf32(vb.y);
            Bs[buf][lc4 * 4 + 2][row] = to_tf32(vb.z);
            Bs[buf][lc4 * 4 + 3][row] = to_tf32(vb.w);
        }
    };

    sts_tiles(0);
    __syncthreads();

    int niter = K / 16;
    for (int kt = 0; kt < niter; ++kt) {
        int cur = kt & 1;

        if (kt + 1 < niter) {
            int off = (kt + 1) * 16;
            ar[0] = *(const float4*)(Ald + off);
            ar[1] = *(const float4*)(Ald + half + off);
            br[0] = *(const float4*)(Bld + off);
            br[1] = *(const float4*)(Bld + half + off);
        }

#pragma unroll
        for (int ks = 0; ks < 16; ks += 8) {
            uint32_t af[4][4];
#pragma unroll
            for (int mt = 0; mt < 4; ++mt) {
                int mrow = wm * 64 + mt * 16 + grp;
                af[mt][0] = __float_as_uint(As[cur][ks + tig    ][mrow]);
                af[mt][1] = __float_as_uint(As[cur][ks + tig    ][mrow + 8]);
                af[mt][2] = __float_as_uint(As[cur][ks + tig + 4][mrow]);
                af[mt][3] = __float_as_uint(As[cur][ks + tig + 4][mrow + 8]);
            }
            uint32_t bf[4][2];
#pragma unroll
            for (int nt = 0; nt < 4; ++nt) {
                int ncol = wn * 32 + nt * 8 + grp;
                bf[nt][0] = __float_as_uint(Bs[cur][ks + tig    ][ncol]);
                bf[nt][1] = __float_as_uint(Bs[cur][ks + tig + 4][ncol]);
            }
#pragma unroll
            for (int mt = 0; mt < 4; ++mt)
#pragma unroll
                for (int nt = 0; nt < 4; ++nt)
                    mma_tf32(acc[mt][nt], af[mt], bf[nt]);
        }

        if (kt + 1 < niter) {
            sts_tiles(cur ^ 1);
            __syncthreads();
        }
    }

    // Epilogue: each warp writes its 64x32 region.
#pragma unroll
    for (int mt = 0; mt < 4; ++mt) {
#pragma unroll
        for (int nt = 0; nt < 4; ++nt) {
            int row = m0 + wm * 64 + mt * 16 + grp;
            int col = n0 + wn * 32 + nt * 8 + 2 * tig;
            float2 v0 = make_float2(acc[mt][nt][0], acc[mt][nt][1]);
            float2 v1 = make_float2(acc[mt][nt][2], acc[mt][nt][3]);
            *(float2*)(C + (size_t)row * N + col) = v0;
            *(float2*)(C + (size_t)(row + 8) * N + col) = v1;
        }
    }
}

// ----------------------------------------------------------------------------
// Flash attention, fp32 (unchanged from passing baseline).
// ----------------------------------------------------------------------------
__global__ __launch_bounds__(256) void attn_kernel(
    const float* __restrict__ qkv, float* __restrict__ vals)
{
    __shared__ float Qs[HD_][64];  // [d][m], pre-scaled by 1/sqrt(HD)
    __shared__ float KP[64][64];   // K phase: [d][n]; P phase: [m][n]
    __shared__ float Vs[64][64];   // [n][d]

    int tid = threadIdx.x;
    int tx = tid & 15;
    int ty = tid >> 4;
    int qb = blockIdx.x;
    int h  = blockIdx.y;
    int b  = blockIdx.z;

    const float* qbase = qkv + (size_t)b * S_ * QKV_N + h * (3 * HD_);

#pragma unroll
    for (int p = 0; p < 4; ++p) {
        int idx = tid + p * 256;
        int n  = (idx >> 1) & 63;
        int d4 = (idx & 1) + ((idx >> 7) << 1);
        float4 v = *(const float4*)(qbase + (size_t)(qb * 64 + n) * QKV_N + d4 * 4);
        Qs[d4 * 4 + 0][n] = v.x * 0.125f;
        Qs[d4 * 4 + 1][n] = v.y * 0.125f;
        Qs[d4 * 4 + 2][n] = v.z * 0.125f;
        Qs[d4 * 4 + 3][n] = v.w * 0.125f;
    }

    float m_i[4], l_i[4], o[4][4];
#pragma unroll
    for (int i = 0; i < 4; i++) {
        m_i[i] = -1e30f;
        l_i[i] = 0.f;
#pragma unroll
        for (int j = 0; j < 4; j++) o[i][j] = 0.f;
    }

    for (int nt = 0; nt < S_; nt += 64) {
        __syncthreads();

#pragma unroll
        for (int p = 0; p < 4; ++p) {
            int idx = tid + p * 256;
            int n  = (idx >> 1) & 63;
            int d4 = (idx & 1) + ((idx >> 7) << 1);
            const float* krow = qbase + HD_ + (size_t)(nt + n) * QKV_N;
            float4 kv = *(const float4*)(krow + d4 * 4);
            KP[d4 * 4 + 0][n] = kv.x; KP[d4 * 4 + 1][n] = kv.y;
            KP[d4 * 4 + 2][n] = kv.z; KP[d4 * 4 + 3][n] = kv.w;
            const float* vrow = qbase + 2 * HD_ + (size_t)(nt + n) * QKV_N;
            *(float4*)&Vs[n][d4 * 4] = *(const float4*)(vrow + d4 * 4);
        }
        __syncthreads();

        float s[4][4];
#pragma unroll
        for (int i = 0; i < 4; i++)
#pragma unroll
            for (int j = 0; j < 4; j++) s[i][j] = 0.f;
#pragma unroll 16
        for (int d = 0; d < HD_; ++d) {
            float4 a = *(const float4*)&Qs[d][ty * 4];
            float4 bb = *(const float4*)&KP[d][tx * 4];
            float av[4] = {a.x, a.y, a.z, a.w};
            float bv[4] = {bb.x, bb.y, bb.z, bb.w};
#pragma unroll
            for (int i = 0; i < 4; i++)
#pragma unroll
                for (int j = 0; j < 4; j++)
                    s[i][j] += av[i] * bv[j];
        }

#pragma unroll
        for (int i = 0; i < 4; i++) {
            float tm = fmaxf(fmaxf(s[i][0], s[i][1]), fmaxf(s[i][2], s[i][3]));
#pragma unroll
            for (int off = 8; off >= 1; off >>= 1)
                tm = fmaxf(tm, __shfl_xor_sync(0xffffffffu, tm, off));
            float mn = fmaxf(m_i[i], tm);
            float fac = __expf(m_i[i] - mn);
            m_i[i] = mn;
            float rs = 0.f;
#pragma unroll
            for (int j = 0; j < 4; j++) {
                s[i][j] = __expf(s[i][j] - mn);
                rs += s[i][j];
            }
#pragma unroll
            for (int off = 8; off >= 1; off >>= 1)
                rs += __shfl_xor_sync(0xffffffffu, rs, off);
            l_i[i] = l_i[i] * fac + rs;
#pragma unroll
            for (int j = 0; j < 4; j++) o[i][j] *= fac;
        }

        __syncthreads();
#pragma unroll
        for (int i = 0; i < 4; i++)
            *(float4*)&KP[ty * 4 + i][tx * 4] =
                make_float4(s[i][0], s[i][1], s[i][2], s[i][3]);
        __syncthreads();

#pragma unroll 8
        for (int n = 0; n < 64; ++n) {
            float4 bv = *(const float4*)&Vs[n][tx * 4];
            float bvv[4] = {bv.x, bv.y, bv.z, bv.w};
            float av[4];
#pragma unroll
            for (int i = 0; i < 4; i++) av[i] = KP[ty * 4 + i][n];
#pragma unroll
            for (int i = 0; i < 4; i++)
#pragma unroll
                for (int j = 0; j < 4; j++)
                    o[i][j] += av[i] * bvv[j];
        }
    }

#pragma unroll
    for (int i = 0; i < 4; i++) {
        float inv = 1.f / l_i[i];
        size_t row = (size_t)b * S_ + qb * 64 + ty * 4 + i;
        float4 v = make_float4(o[i][0] * inv, o[i][1] * inv,
                               o[i][2] * inv, o[i][3] * inv);
        *(float4*)(vals + row * E_ + h * HD_ + tx * 4) = v;
    }
}

// ----------------------------------------------------------------------------
// Launch
// ----------------------------------------------------------------------------
extern "C" void kernel_launch(void* const* d_in, const int* in_sizes, int n_in,
                              void* d_out, int out_size)
{
    (void)in_sizes; (void)n_in; (void)out_size;
    const float* x     = (const float*)d_in[0];
    const float* qkv_w = (const float*)d_in[1];
    const float* o_w   = (const float*)d_in[2];
    float* out = (float*)d_out;

    static float* qkv_buf = nullptr;
    static float* vals_buf = nullptr;
    if (qkv_buf == nullptr) {
        cudaGetSymbolAddress((void**)&qkv_buf, g_qkv);
        cudaGetSymbolAddress((void**)&vals_buf, g_vals);
    }

    dim3 blk(256);
    // 1) qkv = x @ qkv_w^T : [8192,1024] x [3072,1024]^T -> [8192,3072]
    sgemm_tf32<<<dim3(QKV_N / 128, M_TOT / 128), blk>>>(x, qkv_w, qkv_buf,
                                                        M_TOT, QKV_N, D_);
    // 2) attention -> vals [8192, 1024]
    attn_kernel<<<dim3(S_ / 64, NH_, B_), blk>>>(qkv_buf, vals_buf);
    // 3) out = vals @ o_w^T : [8192,1024] x [1024,1024]^T -> [8192,1024]
    sgemm_tf32<<<dim3(E_ / 128, M_TOT / 128), blk>>>(vals_buf, o_w, out,
                                                     M_TOT, E_, D_);
}

// round 5
// speedup vs baseline: 2.6390x; 1.9102x over previous
#include <cuda_runtime.h>
#include <math.h>
#include <stdint.h>

// Problem constants
#define B_   4
#define S_   2048
#define D_   1024
#define E_   1024
#define NH_  16
#define HD_  64
#define QKV_N (3 * E_)       // 3072
#define M_TOT (B_ * S_)      // 8192

// Scratch (device globals — allocation-free per harness rules)
__device__ float g_qkv[(size_t)M_TOT * QKV_N];   // [8192, 3072]
__device__ float g_vals[(size_t)M_TOT * E_];     // [8192, 1024]

// ----------------------------------------------------------------------------
// tf32 helpers
// ----------------------------------------------------------------------------
__device__ __forceinline__ float to_tf32(float x) {
    uint32_t u;
    asm("cvt.rna.tf32.f32 %0, %1;" : "=r"(u) : "f"(x));
    return __uint_as_float(u);
}

__device__ __forceinline__ void mma_tf32(float* c, const uint32_t* a,
                                         const uint32_t* b) {
    asm volatile(
        "mma.sync.aligned.m16n8k8.row.col.f32.tf32.tf32.f32 "
        "{%0,%1,%2,%3},{%4,%5,%6,%7},{%8,%9},{%0,%1,%2,%3};"
        : "+f"(c[0]), "+f"(c[1]), "+f"(c[2]), "+f"(c[3])
        : "r"(a[0]), "r"(a[1]), "r"(a[2]), "r"(a[3]),
          "r"(b[0]), "r"(b[1]));
}

// ----------------------------------------------------------------------------
// TF32 tensor-core GEMM: C = A[M,K] @ B[N,K]^T (both K-contiguous).
// 128x128 block tile, BK=16, 256 threads (8 warps as 2x4), warp tile 64x32.
// ----------------------------------------------------------------------------
__global__ __launch_bounds__(256) void sgemm_tf32(
    const float* __restrict__ A, const float* __restrict__ Bm,
    float* __restrict__ C, int M, int N, int K)
{
    __shared__ float As[2][16][136];
    __shared__ float Bs[2][16][136];

    int tid  = threadIdx.x;
    int lane = tid & 31;
    int warp = tid >> 5;
    int wm = warp & 1;
    int wn = warp >> 1;
    int tig = lane & 3;
    int grp = lane >> 2;

    int m0 = blockIdx.y * 128;
    int n0 = blockIdx.x * 128;

    int lr  = tid >> 2;
    int lc4 = tid & 3;
    const float* Ald = A  + (size_t)(m0 + lr) * K + lc4 * 4;
    const float* Bld = Bm + (size_t)(n0 + lr) * K + lc4 * 4;
    size_t half = (size_t)64 * K;

    float acc[4][4][4];
#pragma unroll
    for (int i = 0; i < 4; i++)
#pragma unroll
        for (int j = 0; j < 4; j++)
#pragma unroll
            for (int r = 0; r < 4; r++) acc[i][j][r] = 0.f;

    float4 ar[2], br[2];
    ar[0] = *(const float4*)(Ald);
    ar[1] = *(const float4*)(Ald + half);
    br[0] = *(const float4*)(Bld);
    br[1] = *(const float4*)(Bld + half);

    auto sts_tiles = [&](int buf) {
#pragma unroll
        for (int p = 0; p < 2; ++p) {
            int row = lr + p * 64;
            float4 va = ar[p];
            As[buf][lc4 * 4 + 0][row] = to_tf32(va.x);
            As[buf][lc4 * 4 + 1][row] = to_tf32(va.y);
            As[buf][lc4 * 4 + 2][row] = to_tf32(va.z);
            As[buf][lc4 * 4 + 3][row] = to_tf32(va.w);
            float4 vb = br[p];
            Bs[buf][lc4 * 4 + 0][row] = to_tf32(vb.x);
            Bs[buf][lc4 * 4 + 1][row] = to_tf32(vb.y);
            Bs[buf][lc4 * 4 + 2][row] = to_tf32(vb.z);
            Bs[buf][lc4 * 4 + 3][row] = to_tf32(vb.w);
        }
    };

    sts_tiles(0);
    __syncthreads();

    int niter = K / 16;
    for (int kt = 0; kt < niter; ++kt) {
        int cur = kt & 1;

        if (kt + 1 < niter) {
            int off = (kt + 1) * 16;
            ar[0] = *(const float4*)(Ald + off);
            ar[1] = *(const float4*)(Ald + half + off);
            br[0] = *(const float4*)(Bld + off);
            br[1] = *(const float4*)(Bld + half + off);
        }

#pragma unroll
        for (int ks = 0; ks < 16; ks += 8) {
            uint32_t af[4][4];
#pragma unroll
            for (int mt = 0; mt < 4; ++mt) {
                int mrow = wm * 64 + mt * 16 + grp;
                af[mt][0] = __float_as_uint(As[cur][ks + tig    ][mrow]);
                af[mt][1] = __float_as_uint(As[cur][ks + tig    ][mrow + 8]);
                af[mt][2] = __float_as_uint(As[cur][ks + tig + 4][mrow]);
                af[mt][3] = __float_as_uint(As[cur][ks + tig + 4][mrow + 8]);
            }
            uint32_t bf[4][2];
#pragma unroll
            for (int nt = 0; nt < 4; ++nt) {
                int ncol = wn * 32 + nt * 8 + grp;
                bf[nt][0] = __float_as_uint(Bs[cur][ks + tig    ][ncol]);
                bf[nt][1] = __float_as_uint(Bs[cur][ks + tig + 4][ncol]);
            }
#pragma unroll
            for (int mt = 0; mt < 4; ++mt)
#pragma unroll
                for (int nt = 0; nt < 4; ++nt)
                    mma_tf32(acc[mt][nt], af[mt], bf[nt]);
        }

        if (kt + 1 < niter) {
            sts_tiles(cur ^ 1);
            __syncthreads();
        }
    }

#pragma unroll
    for (int mt = 0; mt < 4; ++mt) {
#pragma unroll
        for (int nt = 0; nt < 4; ++nt) {
            int row = m0 + wm * 64 + mt * 16 + grp;
            int col = n0 + wn * 32 + nt * 8 + 2 * tig;
            float2 v0 = make_float2(acc[mt][nt][0], acc[mt][nt][1]);
            float2 v1 = make_float2(acc[mt][nt][2], acc[mt][nt][3]);
            *(float2*)(C + (size_t)row * N + col) = v0;
            *(float2*)(C + (size_t)(row + 8) * N + col) = v1;
        }
    }
}

// ----------------------------------------------------------------------------
// Tensor-core flash attention (tf32 mma). One CTA = (b, h, 128-query block).
// 8 warps x 16 query rows. BN=64 keys/iter. Q fragments in registers.
// Dynamic smem 52KB: Pbuf[128][68] (upper 64 rows alias the K tile) +
// Vs[64][72]. All fragment LDS patterns conflict-free.
// ----------------------------------------------------------------------------
#define PSTR 68
#define VSTR 72

__global__ __launch_bounds__(256) void attn_tc(
    const float* __restrict__ qkv, float* __restrict__ vals)
{
    extern __shared__ float sm[];
    float* Pbuf = sm;                       // [128][PSTR]
    float* Ksm  = sm + 64 * PSTR;           // [64][PSTR] (rows 64..127 of Pbuf)
    float* Vsm  = sm + 128 * PSTR;          // [64][VSTR]

    int tid  = threadIdx.x;
    int lane = tid & 31;
    int warp = tid >> 5;
    int grp  = lane >> 2;
    int tig  = lane & 3;

    int qb = blockIdx.x;
    int h  = blockIdx.y;
    int b  = blockIdx.z;

    const float* base = qkv + (size_t)b * S_ * QKV_N + h * (3 * HD_);
    const float* qg = base;
    const float* kg = base + HD_;
    const float* vg = base + 2 * HD_;
    int q0 = qb * 128;

    // ---- Stage Q (scaled, tf32) through Pbuf, then lift to fragments ----
#pragma unroll
    for (int p = 0; p < 8; ++p) {
        int idx = tid + p * 256;            // 0..2047
        int row = idx >> 4;
        int c4  = idx & 15;
        float4 v = *(const float4*)(qg + (size_t)(q0 + row) * QKV_N + c4 * 4);
        float4 t;
        t.x = to_tf32(v.x * 0.125f);
        t.y = to_tf32(v.y * 0.125f);
        t.z = to_tf32(v.z * 0.125f);
        t.w = to_tf32(v.w * 0.125f);
        *(float4*)(Pbuf + row * PSTR + c4 * 4) = t;
    }
    __syncthreads();

    uint32_t qf[8][4];
    {
        int r0 = warp * 16 + grp;
#pragma unroll
        for (int ks = 0; ks < 8; ++ks) {
            qf[ks][0] = __float_as_uint(Pbuf[r0 * PSTR + 8 * ks + tig]);
            qf[ks][1] = __float_as_uint(Pbuf[(r0 + 8) * PSTR + 8 * ks + tig]);
            qf[ks][2] = __float_as_uint(Pbuf[r0 * PSTR + 8 * ks + tig + 4]);
            qf[ks][3] = __float_as_uint(Pbuf[(r0 + 8) * PSTR + 8 * ks + tig + 4]);
        }
    }

    float m_i[2] = {-1e30f, -1e30f};
    float l_i[2] = {0.f, 0.f};
    float oacc[8][4];
#pragma unroll
    for (int nt = 0; nt < 8; ++nt)
#pragma unroll
        for (int r = 0; r < 4; ++r) oacc[nt][r] = 0.f;

    for (int kt = 0; kt < S_; kt += 64) {
        __syncthreads();   // prev PV reads of Pbuf/Vsm done; Q frag reads done

        // ---- Load K tile (tf32) into Ksm, V tile (tf32) into Vsm ----
#pragma unroll
        for (int p = 0; p < 4; ++p) {
            int idx = tid + p * 256;        // 0..1023
            int row = idx >> 4;
            int c4  = idx & 15;
            float4 v = *(const float4*)(kg + (size_t)(kt + row) * QKV_N + c4 * 4);
            float4 t;
            t.x = to_tf32(v.x); t.y = to_tf32(v.y);
            t.z = to_tf32(v.z); t.w = to_tf32(v.w);
            *(float4*)(Ksm + row * PSTR + c4 * 4) = t;
            float4 w = *(const float4*)(vg + (size_t)(kt + row) * QKV_N + c4 * 4);
            float4 u;
            u.x = to_tf32(w.x); u.y = to_tf32(w.y);
            u.z = to_tf32(w.z); u.w = to_tf32(w.w);
            *(float4*)(Vsm + row * VSTR + c4 * 4) = u;
        }
        __syncthreads();

        // ---- S = Q @ K^T  (warp: 16 rows x 64 keys) ----
        float sacc[8][4];
#pragma unroll
        for (int nt = 0; nt < 8; ++nt)
#pragma unroll
            for (int r = 0; r < 4; ++r) sacc[nt][r] = 0.f;

#pragma unroll
        for (int ks = 0; ks < 8; ++ks) {
            uint32_t bf[8][2];
#pragma unroll
            for (int nt = 0; nt < 8; ++nt) {
                bf[nt][0] = __float_as_uint(Ksm[(nt * 8 + grp) * PSTR + 8 * ks + tig]);
                bf[nt][1] = __float_as_uint(Ksm[(nt * 8 + grp) * PSTR + 8 * ks + tig + 4]);
            }
#pragma unroll
            for (int nt = 0; nt < 8; ++nt)
                mma_tf32(sacc[nt], qf[ks], bf[nt]);
        }
        __syncthreads();   // all warps done reading Ksm (aliased w/ Pbuf)

        // ---- Online softmax (rows grp, grp+8 of warp tile) ----
        float mx0 = -1e30f, mx1 = -1e30f;
#pragma unroll
        for (int nt = 0; nt < 8; ++nt) {
            mx0 = fmaxf(mx0, fmaxf(sacc[nt][0], sacc[nt][1]));
            mx1 = fmaxf(mx1, fmaxf(sacc[nt][2], sacc[nt][3]));
        }
        mx0 = fmaxf(mx0, __shfl_xor_sync(0xffffffffu, mx0, 1));
        mx0 = fmaxf(mx0, __shfl_xor_sync(0xffffffffu, mx0, 2));
        mx1 = fmaxf(mx1, __shfl_xor_sync(0xffffffffu, mx1, 1));
        mx1 = fmaxf(mx1, __shfl_xor_sync(0xffffffffu, mx1, 2));

        float mn0 = fmaxf(m_i[0], mx0);
        float mn1 = fmaxf(m_i[1], mx1);
        float f0 = __expf(m_i[0] - mn0);
        float f1 = __expf(m_i[1] - mn1);
        m_i[0] = mn0; m_i[1] = mn1;

        int r0 = warp * 16 + grp;
        float rs0 = 0.f, rs1 = 0.f;
#pragma unroll
        for (int nt = 0; nt < 8; ++nt) {
            float p0 = __expf(sacc[nt][0] - mn0);
            float p1 = __expf(sacc[nt][1] - mn0);
            float p2 = __expf(sacc[nt][2] - mn1);
            float p3 = __expf(sacc[nt][3] - mn1);
            rs0 += p0 + p1;
            rs1 += p2 + p3;
            *(float2*)(Pbuf + r0 * PSTR + nt * 8 + 2 * tig) =
                make_float2(to_tf32(p0), to_tf32(p1));
            *(float2*)(Pbuf + (r0 + 8) * PSTR + nt * 8 + 2 * tig) =
                make_float2(to_tf32(p2), to_tf32(p3));
        }
        rs0 += __shfl_xor_sync(0xffffffffu, rs0, 1);
        rs0 += __shfl_xor_sync(0xffffffffu, rs0, 2);
        rs1 += __shfl_xor_sync(0xffffffffu, rs1, 1);
        rs1 += __shfl_xor_sync(0xffffffffu, rs1, 2);
        l_i[0] = l_i[0] * f0 + rs0;
        l_i[1] = l_i[1] * f1 + rs1;

#pragma unroll
        for (int nt = 0; nt < 8; ++nt) {
            oacc[nt][0] *= f0; oacc[nt][1] *= f0;
            oacc[nt][2] *= f1; oacc[nt][3] *= f1;
        }
        __syncthreads();   // P visible to all warps

        // ---- O += P @ V ----
#pragma unroll
        for (int ks = 0; ks < 8; ++ks) {
            uint32_t af[4];
            af[0] = __float_as_uint(Pbuf[r0 * PSTR + 8 * ks + tig]);
            af[1] = __float_as_uint(Pbuf[(r0 + 8) * PSTR + 8 * ks + tig]);
            af[2] = __float_as_uint(Pbuf[r0 * PSTR + 8 * ks + tig + 4]);
            af[3] = __float_as_uint(Pbuf[(r0 + 8) * PSTR + 8 * ks + tig + 4]);
#pragma unroll
            for (int nt = 0; nt < 8; ++nt) {
                uint32_t bf[2];
                bf[0] = __float_as_uint(Vsm[(8 * ks + tig) * VSTR + nt * 8 + grp]);
                bf[1] = __float_as_uint(Vsm[(8 * ks + tig + 4) * VSTR + nt * 8 + grp]);
                mma_tf32(oacc[nt], af, bf);
            }
        }
    }

    // ---- Epilogue: normalize, write vals[b, q, h*64 + d] ----
    float inv0 = 1.f / l_i[0];
    float inv1 = 1.f / l_i[1];
    size_t row0 = (size_t)b * S_ + q0 + warp * 16 + grp;
#pragma unroll
    for (int nt = 0; nt < 8; ++nt) {
        int col = h * HD_ + nt * 8 + 2 * tig;
        *(float2*)(vals + row0 * E_ + col) =
            make_float2(oacc[nt][0] * inv0, oacc[nt][1] * inv0);
        *(float2*)(vals + (row0 + 8) * E_ + col) =
            make_float2(oacc[nt][2] * inv1, oacc[nt][3] * inv1);
    }
}

// ----------------------------------------------------------------------------
// Launch
// ----------------------------------------------------------------------------
#define ATTN_SMEM ((128 * PSTR + 64 * VSTR) * 4)   // 53248 bytes

extern "C" void kernel_launch(void* const* d_in, const int* in_sizes, int n_in,
                              void* d_out, int out_size)
{
    (void)in_sizes; (void)n_in; (void)out_size;
    const float* x     = (const float*)d_in[0];
    const float* qkv_w = (const float*)d_in[1];
    const float* o_w   = (const float*)d_in[2];
    float* out = (float*)d_out;

    static float* qkv_buf = nullptr;
    static float* vals_buf = nullptr;
    if (qkv_buf == nullptr) {
        cudaGetSymbolAddress((void**)&qkv_buf, g_qkv);
        cudaGetSymbolAddress((void**)&vals_buf, g_vals);
        cudaFuncSetAttribute(attn_tc,
                             cudaFuncAttributeMaxDynamicSharedMemorySize,
                             ATTN_SMEM);
    }

    dim3 blk(256);
    // 1) qkv = x @ qkv_w^T
    sgemm_tf32<<<dim3(QKV_N / 128, M_TOT / 128), blk>>>(x, qkv_w, qkv_buf,
                                                        M_TOT, QKV_N, D_);
    // 2) attention -> vals
    attn_tc<<<dim3(S_ / 128, NH_, B_), blk, ATTN_SMEM>>>(qkv_buf, vals_buf);
    // 3) out = vals @ o_w^T
    sgemm_tf32<<<dim3(E_ / 128, M_TOT / 128), blk>>>(vals_buf, o_w, out,
                                                     M_TOT, E_, D_);
}